// round 2
// baseline (speedup 1.0000x reference)
#include <cuda_runtime.h>

// ============================================================================
// 2-layer LSTM (B=256, T=256, IN=256, U=512) + Dense(1), fp32 persistent kernel.
//
// Strategy: single persistent cooperative kernel, 128 CTAs (32 unit-blocks x
// 4 batch-blocks). Each CTA owns a (64-batch x 16-unit) state tile; cell state
// c0/c1 lives in registers for all 256 steps. Hidden states h0/h1 are
// double-buffered in __device__ globals; 2 gmem barriers per step.
// GEMM: smem-tiled, Kc=64, register prefetch of next chunk overlapped with FMA.
// ============================================================================

#define TSEQ 256
#define NB   256
#define DIN  256
#define NU   512
#define NG   2048   // 4*NU

#define NCTA 128
#define NTHR 256
#define TM   64     // batch rows per CTA
#define TU   16     // units per CTA (=> 64 gate columns)
#define KC   64     // K chunk
#define ASTR 68     // As row stride (pad for alignment/conflicts)

__device__ float    g_h0[2][NB][NU];
__device__ float    g_h1[2][NB][NU];
__device__ unsigned g_bar[1024];

__device__ __forceinline__ float sigf(float x) { return 1.0f / (1.0f + __expf(-x)); }
__device__ __forceinline__ float tanhfast(float x) { return 2.0f / (1.0f + __expf(-2.0f * x)) - 1.0f; }

// Zero h buffers + barrier slots every launch (graph-replay deterministic).
__global__ void init_kernel() {
    int i = blockIdx.x * blockDim.x + threadIdx.x;   // grid 512 x 256 = 131072
    float* h0 = &g_h0[0][0][0];
    float* h1 = &g_h1[0][0][0];
    h0[i] = 0.0f; h0[i + 131072] = 0.0f;
    h1[i] = 0.0f; h1[i + 131072] = 0.0f;
    if (i < 1024) g_bar[i] = 0u;
}

// Grid-wide barrier: single-use slot per barrier instance, reset by init_kernel.
__device__ __forceinline__ void gbar(int slot) {
    __syncthreads();
    if (threadIdx.x == 0) {
        __threadfence();                         // release (flushes, orders prior stores)
        unsigned arrived = atomicAdd(&g_bar[slot], 1u) + 1u;
        if (arrived < NCTA) {
            while (*((volatile unsigned*)&g_bar[slot]) < NCTA) __nanosleep(64);
        }
        __threadfence();                         // acquire (CCTL.IVALL invalidates L1D)
    }
    __syncthreads();
}

struct Srcs { const float* A; int sA; const float* B; };

__device__ __forceinline__ Srcs get_srcs(
    int layer, int c, const float* xt,
    const float* h0c, const float* h0n, const float* h1c,
    const float* W0, const float* U0, const float* W1, const float* U1)
{
    Srcs s;
    if (layer == 0) {
        if (c < 4) { s.A = xt  + c * KC;        s.sA = TSEQ * DIN; s.B = W0 + c * KC * NG; }
        else       { s.A = h0c + (c - 4) * KC;  s.sA = NU;         s.B = U0 + (c - 4) * KC * NG; }
    } else {
        if (c < 8) { s.A = h0n + c * KC;        s.sA = NU;         s.B = W1 + c * KC * NG; }
        else       { s.A = h1c + (c - 8) * KC;  s.sA = NU;         s.B = U1 + (c - 8) * KC * NG; }
    }
    return s;
}

// Fetch next chunk (global -> registers). A tile: [64 rows x 64 k]; B: [64 k x 64 cols].
__device__ __forceinline__ void fetch(const Srcs& s, int m0, int u0,
                                      float4 ra[4], float4 rb[4])
{
    int tid = threadIdx.x;
#pragma unroll
    for (int i = 0; i < 4; i++) {
        int idx = i * NTHR + tid;
        int m  = idx >> 4;
        int kf = (idx & 15) << 2;
        ra[i] = *(const float4*)(s.A + (m0 + m) * s.sA + kf);
    }
#pragma unroll
    for (int i = 0; i < 4; i++) {
        int idx = i * NTHR + tid;
        int k  = idx >> 4;
        int jf = (idx & 15) << 2;
        rb[i] = *(const float4*)(s.B + k * NG + (jf >> 4) * NU + u0 + (jf & 15));
    }
}

// Registers -> smem. As is m-major [64][ASTR]; Bs is k-major [64][64].
__device__ __forceinline__ void stage(const float4 ra[4], const float4 rb[4],
                                      float* As, float* Bs)
{
    int tid = threadIdx.x;
#pragma unroll
    for (int i = 0; i < 4; i++) {
        int idx = i * NTHR + tid;
        int m  = idx >> 4;
        int kf = (idx & 15) << 2;
        *(float4*)(As + m * ASTR + kf) = ra[i];
    }
#pragma unroll
    for (int i = 0; i < 4; i++) {
        int idx = i * NTHR + tid;
        int k  = idx >> 4;
        int jf = (idx & 15) << 2;
        *(float4*)(Bs + k * 64 + jf) = rb[i];
    }
}

// 4 rows x 4 gates micro-tile over one KC chunk.
__device__ __forceinline__ void mm(const float* __restrict__ As,
                                   const float* __restrict__ Bs,
                                   float acc[4][4], int ul, int rg)
{
    const float* a = As + rg * 4 * ASTR;
#pragma unroll 8
    for (int k = 0; k < KC; k++) {
        float bv0 = Bs[k * 64 + ul];
        float bv1 = Bs[k * 64 + ul + 16];
        float bv2 = Bs[k * 64 + ul + 32];
        float bv3 = Bs[k * 64 + ul + 48];
        float a0 = a[k];
        float a1 = a[k + ASTR];
        float a2 = a[k + 2 * ASTR];
        float a3 = a[k + 3 * ASTR];
        acc[0][0] += a0 * bv0; acc[0][1] += a0 * bv1; acc[0][2] += a0 * bv2; acc[0][3] += a0 * bv3;
        acc[1][0] += a1 * bv0; acc[1][1] += a1 * bv1; acc[1][2] += a1 * bv2; acc[1][3] += a1 * bv3;
        acc[2][0] += a2 * bv0; acc[2][1] += a2 * bv1; acc[2][2] += a2 * bv2; acc[2][3] += a2 * bv3;
        acc[3][0] += a3 * bv0; acc[3][1] += a3 * bv1; acc[3][2] += a3 * bv2; acc[3][3] += a3 * bv3;
    }
}

__global__ void __launch_bounds__(NTHR) lstm_kernel(
    const float* __restrict__ x,
    const float* __restrict__ W0, const float* __restrict__ U0, const float* __restrict__ b0,
    const float* __restrict__ W1, const float* __restrict__ U1, const float* __restrict__ b1)
{
    __shared__ float As[TM * ASTR];
    __shared__ float Bs[KC * 64];

    int bx = blockIdx.x;
    int ub = bx & 31, mb = bx >> 5;
    int u0 = ub * TU, m0 = mb * TM;
    int tid = threadIdx.x;
    int ul = tid & 15, rg = tid >> 4;
    int ug = u0 + ul;

    float bias0[4], bias1[4];
#pragma unroll
    for (int g = 0; g < 4; g++) { bias0[g] = b0[g * NU + ug]; bias1[g] = b1[g * NU + ug]; }

    float c0r[4] = {0.f, 0.f, 0.f, 0.f};
    float c1r[4] = {0.f, 0.f, 0.f, 0.f};

    int slot = 0;
    for (int t = 0; t < TSEQ; t++) {
        int p = t & 1;
        const float* h0c = &g_h0[p][0][0];
        float*       h0n = &g_h0[p ^ 1][0][0];
        const float* h1c = &g_h1[p][0][0];
        float*       h1n = &g_h1[p ^ 1][0][0];
        const float* xt  = x + t * DIN;

        // ---------------- layer 0: z0 = [x_t, h0] @ [W0; U0] + b0 ----------------
        {
            float acc[4][4];
#pragma unroll
            for (int r = 0; r < 4; r++)
#pragma unroll
                for (int g = 0; g < 4; g++) acc[r][g] = bias0[g];

            float4 ra[4], rb[4];
            Srcs s = get_srcs(0, 0, xt, h0c, h0n, h1c, W0, U0, W1, U1);
            fetch(s, m0, u0, ra, rb);
#pragma unroll 1
            for (int c = 0; c < 12; c++) {
                __syncthreads();
                stage(ra, rb, As, Bs);
                __syncthreads();
                if (c + 1 < 12) {
                    Srcs sn = get_srcs(0, c + 1, xt, h0c, h0n, h1c, W0, U0, W1, U1);
                    fetch(sn, m0, u0, ra, rb);
                }
                mm(As, Bs, acc, ul, rg);
            }
            // cell 0: gates order i, f, g, o
#pragma unroll
            for (int r = 0; r < 4; r++) {
                float cn = sigf(acc[r][1]) * c0r[r] + sigf(acc[r][0]) * tanhfast(acc[r][2]);
                c0r[r] = cn;
                float h = sigf(acc[r][3]) * tanhfast(cn);
                h0n[(m0 + rg * 4 + r) * NU + ug] = h;
            }
        }
        gbar(slot++);

        // ---------------- layer 1: z1 = [h0_new, h1] @ [W1; U1] + b1 ----------------
        {
            float acc[4][4];
#pragma unroll
            for (int r = 0; r < 4; r++)
#pragma unroll
                for (int g = 0; g < 4; g++) acc[r][g] = bias1[g];

            float4 ra[4], rb[4];
            Srcs s = get_srcs(1, 0, xt, h0c, h0n, h1c, W0, U0, W1, U1);
            fetch(s, m0, u0, ra, rb);
#pragma unroll 1
            for (int c = 0; c < 16; c++) {
                __syncthreads();
                stage(ra, rb, As, Bs);
                __syncthreads();
                if (c + 1 < 16) {
                    Srcs sn = get_srcs(1, c + 1, xt, h0c, h0n, h1c, W0, U0, W1, U1);
                    fetch(sn, m0, u0, ra, rb);
                }
                mm(As, Bs, acc, ul, rg);
            }
#pragma unroll
            for (int r = 0; r < 4; r++) {
                float cn = sigf(acc[r][1]) * c1r[r] + sigf(acc[r][0]) * tanhfast(acc[r][2]);
                c1r[r] = cn;
                float h = sigf(acc[r][3]) * tanhfast(cn);
                h1n[(m0 + rg * 4 + r) * NU + ug] = h;
            }
        }
        gbar(slot++);
    }
}

// Final head: out[b] = h1_final[b,:] @ Wfc + bfc.  Final h1 is in buffer 0 (T even).
__global__ void out_kernel(const float* __restrict__ Wfc,
                           const float* __restrict__ bfc,
                           float* __restrict__ out)
{
    int warp = threadIdx.x >> 5, lane = threadIdx.x & 31;
    int wglob = blockIdx.x * 8 + warp;          // 0..63
#pragma unroll
    for (int i = 0; i < 4; i++) {
        int b = wglob * 4 + i;                  // 0..255
        float s = 0.f;
        for (int u = lane; u < NU; u += 32) s += g_h1[0][b][u] * Wfc[u];
#pragma unroll
        for (int off = 16; off; off >>= 1) s += __shfl_down_sync(0xffffffffu, s, off);
        if (lane == 0) out[b] = s + bfc[0];
    }
}

extern "C" void kernel_launch(void* const* d_in, const int* in_sizes, int n_in,
                              void* d_out, int out_size)
{
    const float* x   = (const float*)d_in[0];
    const float* W0  = (const float*)d_in[1];
    const float* U0  = (const float*)d_in[2];
    const float* b0  = (const float*)d_in[3];
    const float* W1  = (const float*)d_in[4];
    const float* U1  = (const float*)d_in[5];
    const float* b1  = (const float*)d_in[6];
    const float* Wfc = (const float*)d_in[7];
    const float* bfc = (const float*)d_in[8];

    init_kernel<<<512, 256>>>();
    lstm_kernel<<<NCTA, NTHR>>>(x, W0, U0, b0, W1, U1, b1);
    out_kernel<<<8, 256>>>(Wfc, bfc, (float*)d_out);
}

// round 3
// speedup vs baseline: 1.0111x; 1.0111x over previous
#include <cuda_runtime.h>

// ============================================================================
// 2-layer LSTM (B=256, T=256, IN=256, U=512) + Dense(1), persistent kernel.
// R2: packed fp32 FMA (fma.rn.f32x2) -> 128 MAC/cyc/SM (2x scalar FFMA rate).
// Bs staged j-major (stride 66) so B k-pairs are single LDS.64 loads.
// ============================================================================

#define TSEQ 256
#define NB   256
#define DIN  256
#define NU   512
#define NG   2048   // 4*NU

#define NCTA 128
#define NTHR 256
#define TM   64     // batch rows per CTA
#define TU   16     // units per CTA (=> 64 gate columns)
#define KC   64     // K chunk
#define ASTR 68     // As row stride (even: aligned LDS.64; pad vs conflicts)
#define BSTR 66     // Bs row stride (j-major, even for LDS.64, conflict-free reads)

typedef unsigned long long u64t;

__device__ float    g_h0[2][NB][NU];
__device__ float    g_h1[2][NB][NU];
__device__ unsigned g_bar[1024];

__device__ __forceinline__ float sigf(float x) { return 1.0f / (1.0f + __expf(-x)); }
__device__ __forceinline__ float tanhfast(float x) { return 2.0f / (1.0f + __expf(-2.0f * x)) - 1.0f; }

__device__ __forceinline__ u64t fma2(u64t a, u64t b, u64t c) {
    u64t d;
    asm("fma.rn.f32x2 %0, %1, %2, %3;" : "=l"(d) : "l"(a), "l"(b), "l"(c));
    return d;
}

__device__ __forceinline__ float red2(u64t v) {
    float2 f;
    asm("mov.b64 {%0, %1}, %2;" : "=f"(f.x), "=f"(f.y) : "l"(v));
    return f.x + f.y;
}

// Zero h buffers + barrier slots every launch (graph-replay deterministic).
__global__ void init_kernel() {
    int i = blockIdx.x * blockDim.x + threadIdx.x;   // grid 512 x 256 = 131072
    float* h0 = &g_h0[0][0][0];
    float* h1 = &g_h1[0][0][0];
    h0[i] = 0.0f; h0[i + 131072] = 0.0f;
    h1[i] = 0.0f; h1[i + 131072] = 0.0f;
    if (i < 1024) g_bar[i] = 0u;
}

// Grid-wide barrier: single-use slot per barrier instance, reset by init_kernel.
__device__ __forceinline__ void gbar(int slot) {
    __syncthreads();
    if (threadIdx.x == 0) {
        __threadfence();
        unsigned arrived = atomicAdd(&g_bar[slot], 1u) + 1u;
        if (arrived < NCTA) {
            while (*((volatile unsigned*)&g_bar[slot]) < NCTA) __nanosleep(64);
        }
        __threadfence();
    }
    __syncthreads();
}

struct Srcs { const float* A; int sA; const float* B; };

__device__ __forceinline__ Srcs get_srcs(
    int layer, int c, const float* xt,
    const float* h0c, const float* h0n, const float* h1c,
    const float* W0, const float* U0, const float* W1, const float* U1)
{
    Srcs s;
    if (layer == 0) {
        if (c < 4) { s.A = xt  + c * KC;        s.sA = TSEQ * DIN; s.B = W0 + c * KC * NG; }
        else       { s.A = h0c + (c - 4) * KC;  s.sA = NU;         s.B = U0 + (c - 4) * KC * NG; }
    } else {
        if (c < 8) { s.A = h0n + c * KC;        s.sA = NU;         s.B = W1 + c * KC * NG; }
        else       { s.A = h1c + (c - 8) * KC;  s.sA = NU;         s.B = U1 + (c - 8) * KC * NG; }
    }
    return s;
}

// Fetch next chunk (global -> registers). A tile: [64 rows x 64 k]; B: [64 k x 64 cols].
__device__ __forceinline__ void fetch(const Srcs& s, int m0, int u0,
                                      float4 ra[4], float4 rb[4])
{
    int tid = threadIdx.x;
#pragma unroll
    for (int i = 0; i < 4; i++) {
        int idx = i * NTHR + tid;
        int m  = idx >> 4;
        int kf = (idx & 15) << 2;
        ra[i] = *(const float4*)(s.A + (m0 + m) * s.sA + kf);
    }
#pragma unroll
    for (int i = 0; i < 4; i++) {
        int idx = i * NTHR + tid;
        int k  = idx >> 4;
        int jf = (idx & 15) << 2;
        rb[i] = *(const float4*)(s.B + k * NG + (jf >> 4) * NU + u0 + (jf & 15));
    }
}

// Registers -> smem. As is m-major [64][ASTR]; Bs is j-major [64][BSTR].
__device__ __forceinline__ void stage(const float4 ra[4], const float4 rb[4],
                                      float* As, float* Bs)
{
    int tid = threadIdx.x;
#pragma unroll
    for (int i = 0; i < 4; i++) {
        int idx = i * NTHR + tid;
        int m  = idx >> 4;
        int kf = (idx & 15) << 2;
        *(float4*)(As + m * ASTR + kf) = ra[i];
    }
#pragma unroll
    for (int i = 0; i < 4; i++) {
        int idx = i * NTHR + tid;
        int k  = idx >> 4;
        int jf = (idx & 15) << 2;
        Bs[(jf + 0) * BSTR + k] = rb[i].x;
        Bs[(jf + 1) * BSTR + k] = rb[i].y;
        Bs[(jf + 2) * BSTR + k] = rb[i].z;
        Bs[(jf + 3) * BSTR + k] = rb[i].w;
    }
}

// 4 rows x 4 gates micro-tile over one KC chunk, packed f32x2 over k-pairs.
__device__ __forceinline__ void mm2(const float* __restrict__ As,
                                    const float* __restrict__ Bs,
                                    u64t acc[4][4], int ul, int rg)
{
    const float* a = As + rg * 4 * ASTR;
    const float* b = Bs + ul * BSTR;
#pragma unroll 8
    for (int k = 0; k < KC; k += 2) {
        u64t bv0 = *(const u64t*)(b + k);
        u64t bv1 = *(const u64t*)(b + 16 * BSTR + k);
        u64t bv2 = *(const u64t*)(b + 32 * BSTR + k);
        u64t bv3 = *(const u64t*)(b + 48 * BSTR + k);
        u64t a0  = *(const u64t*)(a + k);
        u64t a1  = *(const u64t*)(a + ASTR + k);
        u64t a2  = *(const u64t*)(a + 2 * ASTR + k);
        u64t a3  = *(const u64t*)(a + 3 * ASTR + k);
        acc[0][0] = fma2(a0, bv0, acc[0][0]); acc[0][1] = fma2(a0, bv1, acc[0][1]);
        acc[0][2] = fma2(a0, bv2, acc[0][2]); acc[0][3] = fma2(a0, bv3, acc[0][3]);
        acc[1][0] = fma2(a1, bv0, acc[1][0]); acc[1][1] = fma2(a1, bv1, acc[1][1]);
        acc[1][2] = fma2(a1, bv2, acc[1][2]); acc[1][3] = fma2(a1, bv3, acc[1][3]);
        acc[2][0] = fma2(a2, bv0, acc[2][0]); acc[2][1] = fma2(a2, bv1, acc[2][1]);
        acc[2][2] = fma2(a2, bv2, acc[2][2]); acc[2][3] = fma2(a2, bv3, acc[2][3]);
        acc[3][0] = fma2(a3, bv0, acc[3][0]); acc[3][1] = fma2(a3, bv1, acc[3][1]);
        acc[3][2] = fma2(a3, bv2, acc[3][2]); acc[3][3] = fma2(a3, bv3, acc[3][3]);
    }
}

__global__ void __launch_bounds__(NTHR) lstm_kernel(
    const float* __restrict__ x,
    const float* __restrict__ W0, const float* __restrict__ U0, const float* __restrict__ b0,
    const float* __restrict__ W1, const float* __restrict__ U1, const float* __restrict__ b1)
{
    __shared__ __align__(16) float As[TM * ASTR];
    __shared__ __align__(16) float Bs[64 * BSTR];

    int bx = blockIdx.x;
    int ub = bx & 31, mb = bx >> 5;
    int u0 = ub * TU, m0 = mb * TM;
    int tid = threadIdx.x;
    int ul = tid & 15, rg = tid >> 4;
    int ug = u0 + ul;

    float bias0[4], bias1[4];
#pragma unroll
    for (int g = 0; g < 4; g++) { bias0[g] = b0[g * NU + ug]; bias1[g] = b1[g * NU + ug]; }

    float c0r[4] = {0.f, 0.f, 0.f, 0.f};
    float c1r[4] = {0.f, 0.f, 0.f, 0.f};

    int slot = 0;
    for (int t = 0; t < TSEQ; t++) {
        int p = t & 1;
        const float* h0c = &g_h0[p][0][0];
        float*       h0n = &g_h0[p ^ 1][0][0];
        const float* h1c = &g_h1[p][0][0];
        float*       h1n = &g_h1[p ^ 1][0][0];
        const float* xt  = x + t * DIN;

        // ---------------- layer 0: z0 = [x_t, h0] @ [W0; U0] + b0 ----------------
        {
            u64t acc[4][4];
#pragma unroll
            for (int r = 0; r < 4; r++)
#pragma unroll
                for (int g = 0; g < 4; g++) acc[r][g] = 0ull;

            float4 ra[4], rb[4];
            Srcs s = get_srcs(0, 0, xt, h0c, h0n, h1c, W0, U0, W1, U1);
            fetch(s, m0, u0, ra, rb);
#pragma unroll 1
            for (int c = 0; c < 12; c++) {
                __syncthreads();
                stage(ra, rb, As, Bs);
                __syncthreads();
                if (c + 1 < 12) {
                    Srcs sn = get_srcs(0, c + 1, xt, h0c, h0n, h1c, W0, U0, W1, U1);
                    fetch(sn, m0, u0, ra, rb);
                }
                mm2(As, Bs, acc, ul, rg);
            }
            // cell 0: gates order i, f, g, o
#pragma unroll
            for (int r = 0; r < 4; r++) {
                float zi = red2(acc[r][0]) + bias0[0];
                float zf = red2(acc[r][1]) + bias0[1];
                float zg = red2(acc[r][2]) + bias0[2];
                float zo = red2(acc[r][3]) + bias0[3];
                float cn = sigf(zf) * c0r[r] + sigf(zi) * tanhfast(zg);
                c0r[r] = cn;
                float h = sigf(zo) * tanhfast(cn);
                h0n[(m0 + rg * 4 + r) * NU + ug] = h;
            }
        }
        gbar(slot++);

        // ---------------- layer 1: z1 = [h0_new, h1] @ [W1; U1] + b1 ----------------
        {
            u64t acc[4][4];
#pragma unroll
            for (int r = 0; r < 4; r++)
#pragma unroll
                for (int g = 0; g < 4; g++) acc[r][g] = 0ull;

            float4 ra[4], rb[4];
            Srcs s = get_srcs(1, 0, xt, h0c, h0n, h1c, W0, U0, W1, U1);
            fetch(s, m0, u0, ra, rb);
#pragma unroll 1
            for (int c = 0; c < 16; c++) {
                __syncthreads();
                stage(ra, rb, As, Bs);
                __syncthreads();
                if (c + 1 < 16) {
                    Srcs sn = get_srcs(1, c + 1, xt, h0c, h0n, h1c, W0, U0, W1, U1);
                    fetch(sn, m0, u0, ra, rb);
                }
                mm2(As, Bs, acc, ul, rg);
            }
#pragma unroll
            for (int r = 0; r < 4; r++) {
                float zi = red2(acc[r][0]) + bias1[0];
                float zf = red2(acc[r][1]) + bias1[1];
                float zg = red2(acc[r][2]) + bias1[2];
                float zo = red2(acc[r][3]) + bias1[3];
                float cn = sigf(zf) * c1r[r] + sigf(zi) * tanhfast(zg);
                c1r[r] = cn;
                float h = sigf(zo) * tanhfast(cn);
                h1n[(m0 + rg * 4 + r) * NU + ug] = h;
            }
        }
        gbar(slot++);
    }
}

// Final head: out[b] = h1_final[b,:] @ Wfc + bfc.  Final h1 is in buffer 0 (T even).
__global__ void out_kernel(const float* __restrict__ Wfc,
                           const float* __restrict__ bfc,
                           float* __restrict__ out)
{
    int warp = threadIdx.x >> 5, lane = threadIdx.x & 31;
    int wglob = blockIdx.x * 8 + warp;          // 0..63
#pragma unroll
    for (int i = 0; i < 4; i++) {
        int b = wglob * 4 + i;                  // 0..255
        float s = 0.f;
        for (int u = lane; u < NU; u += 32) s += g_h1[0][b][u] * Wfc[u];
#pragma unroll
        for (int off = 16; off; off >>= 1) s += __shfl_down_sync(0xffffffffu, s, off);
        if (lane == 0) out[b] = s + bfc[0];
    }
}

extern "C" void kernel_launch(void* const* d_in, const int* in_sizes, int n_in,
                              void* d_out, int out_size)
{
    const float* x   = (const float*)d_in[0];
    const float* W0  = (const float*)d_in[1];
    const float* U0  = (const float*)d_in[2];
    const float* b0  = (const float*)d_in[3];
    const float* W1  = (const float*)d_in[4];
    const float* U1  = (const float*)d_in[5];
    const float* b1  = (const float*)d_in[6];
    const float* Wfc = (const float*)d_in[7];
    const float* bfc = (const float*)d_in[8];

    init_kernel<<<512, 256>>>();
    lstm_kernel<<<NCTA, NTHR>>>(x, W0, U0, b0, W1, U1, b1);
    out_kernel<<<8, 256>>>(Wfc, bfc, (float*)d_out);
}

// round 5
// speedup vs baseline: 1.9625x; 1.9409x over previous
#include <cuda_runtime.h>
#include <cuda_fp16.h>
#include <cstdint>

// ============================================================================
// 2-layer LSTM (B=256, T=256, IN=256, U=512) + Dense(1).
// R4: warp-level mma.sync.m16n8k16 (fp16 split-2, fp32 acc) — sm_103-family
// safe (no 'a'-gated instructions). 128 persistent CTAs (4 mb x 32 ub),
// CTA tile = 64 batch rows x 16 units (64 gate cols, n = unit*4 + gate).
// Weights pre-packed into mma B-fragment order (direct LDG.128, no smem).
// A (x/h) pre-split into fp16 hi/lo planes; staged via smem, ldS fragments.
// c-state in registers; h stored as fp16 hi/lo planes; 2 grid barriers/step.
// ============================================================================

#define TSEQ 256
#define NB   256
#define DIN  256
#define NU   512
#define NCTA 128
#define NTHR 256

// ---- device state ----
__device__ __align__(16) __half g_xh[NB * TSEQ * DIN];
__device__ __align__(16) __half g_xl[NB * TSEQ * DIN];
__device__ __align__(16) __half g_h0h[2][NB][NU];
__device__ __align__(16) __half g_h0l[2][NB][NU];
__device__ __align__(16) __half g_h1h[2][NB][NU];
__device__ __align__(16) __half g_h1l[2][NB][NU];
__device__ unsigned g_bar[1024];

// packed weight fragments: [ub][kt][n8][lane] -> 16B {b0h,b1h,b0l,b1l}
__device__ __align__(16) uint4 g_W0pk[32 * 16 * 8 * 32];
__device__ __align__(16) uint4 g_U0pk[32 * 32 * 8 * 32];
__device__ __align__(16) uint4 g_W1pk[32 * 32 * 8 * 32];
__device__ __align__(16) uint4 g_U1pk[32 * 32 * 8 * 32];

__device__ __forceinline__ float sigf(float x) { return 1.0f / (1.0f + __expf(-x)); }
__device__ __forceinline__ float tanhfast(float x) { return 2.0f / (1.0f + __expf(-2.0f * x)) - 1.0f; }

#define MMA16816(d, a0, a1, a2, a3, bb0, bb1)                                   \
    asm volatile("mma.sync.aligned.m16n8k16.row.col.f32.f16.f16.f32 "           \
        "{%0,%1,%2,%3}, {%4,%5,%6,%7}, {%8,%9}, {%0,%1,%2,%3};"                 \
        : "+f"((d)[0]), "+f"((d)[1]), "+f"((d)[2]), "+f"((d)[3])                \
        : "r"(a0), "r"(a1), "r"(a2), "r"(a3), "r"(bb0), "r"(bb1))

// ---------------------------------------------------------------------------
// prep kernels (run every launch; deterministic)
// ---------------------------------------------------------------------------
__global__ void split_x_kernel(const float* __restrict__ x) {
    int i = blockIdx.x * blockDim.x + threadIdx.x;      // 65536 x 256 = 16.7M
    float v = x[i];
    __half hi = __float2half(v);
    g_xh[i] = hi;
    g_xl[i] = __float2half(v - __half2float(hi));
    if (i < 1024) g_bar[i] = 0u;
    if (i < 262144) {
        ((__half*)g_h0h)[i] = __ushort_as_half(0);
        ((__half*)g_h0l)[i] = __ushort_as_half(0);
        ((__half*)g_h1h)[i] = __ushort_as_half(0);
        ((__half*)g_h1l)[i] = __ushort_as_half(0);
    }
}

__device__ __forceinline__ uint32_t pack_hl(float v0, float v1, int lo) {
    __half h0 = __float2half(v0), h1 = __float2half(v1);
    if (lo) {
        h0 = __float2half(v0 - __half2float(h0));
        h1 = __float2half(v1 - __half2float(h1));
    }
    __half2 p = __halves2half2(h0, h1);
    return *(uint32_t*)&p;
}

// pack W0/U0/W1/U1 into fragment order. id covers 32ub x 112kt x 8n8 x 32lane.
__global__ void pack_w_kernel(const float* __restrict__ W0, const float* __restrict__ U0,
                              const float* __restrict__ W1, const float* __restrict__ U1) {
    int id = blockIdx.x * blockDim.x + threadIdx.x;     // 3584 x 256 = 917504
    int lane = id & 31;
    int n8   = (id >> 5) & 7;
    int rest = id >> 8;                                  // 0 .. 32*112-1
    int ktg  = rest % 112;
    int ub   = rest / 112;

    const float* M; uint4* dst; int kt;
    if      (ktg < 16) { M = W0; kt = ktg;      dst = g_W0pk + (((ub * 16 + kt) * 8 + n8) * 32 + lane); }
    else if (ktg < 48) { M = U0; kt = ktg - 16; dst = g_U0pk + (((ub * 32 + kt) * 8 + n8) * 32 + lane); }
    else if (ktg < 80) { M = W1; kt = ktg - 48; dst = g_W1pk + (((ub * 32 + kt) * 8 + n8) * 32 + lane); }
    else               { M = U1; kt = ktg - 80; dst = g_U1pk + (((ub * 32 + kt) * 8 + n8) * 32 + lane); }

    int n = n8 * 8 + (lane >> 2);        // local col 0..63, n = f*4 + g
    int f = n >> 2, g = n & 3;
    int col = g * NU + ub * 16 + f;
    int k0 = kt * 16 + (lane & 3) * 2;

    float v00 = M[(size_t)(k0 + 0) * 2048 + col];
    float v01 = M[(size_t)(k0 + 1) * 2048 + col];
    float v10 = M[(size_t)(k0 + 8) * 2048 + col];
    float v11 = M[(size_t)(k0 + 9) * 2048 + col];

    uint4 o;
    o.x = pack_hl(v00, v01, 0);
    o.y = pack_hl(v10, v11, 0);
    o.z = pack_hl(v00, v01, 1);
    o.w = pack_hl(v10, v11, 1);
    *dst = o;
}

// ---------------------------------------------------------------------------
__device__ __forceinline__ void gbar(int slot) {
    __syncthreads();
    if (threadIdx.x == 0) {
        __threadfence();
        unsigned arr = atomicAdd(&g_bar[slot], 1u) + 1u;
        if (arr < NCTA) {
            while (*((volatile unsigned*)&g_bar[slot]) < NCTA) __nanosleep(64);
        }
        __threadfence();
    }
    __syncthreads();
}

// A staging: fetch chunk (64 rows x 64 k, hi+lo) into regs, then STS.
// smem layout: uint32 [64 rows][36 words] per plane (word = 2 halves along k).
__device__ __forceinline__ void fetchA(const __half* hi, const __half* lo,
                                       int stride, int m0, uint4 ra[4]) {
    int tid = threadIdx.x;
#pragma unroll
    for (int i = 0; i < 4; i++) {
        int idx = i * NTHR + tid;
        int pl = idx >> 9, v = idx & 511;
        int row = v >> 3, q = v & 7;
        const __half* p = (pl ? lo : hi) + (size_t)(m0 + row) * stride + q * 8;
        ra[i] = *(const uint4*)p;
    }
}
__device__ __forceinline__ void storeA(uint32_t* sAh, uint32_t* sAl, const uint4 ra[4]) {
    int tid = threadIdx.x;
#pragma unroll
    for (int i = 0; i < 4; i++) {
        int idx = i * NTHR + tid;
        int pl = idx >> 9, v = idx & 511;
        int row = v >> 3, q = v & 7;
        *(uint4*)((pl ? sAl : sAh) + row * 36 + q * 4) = ra[i];
    }
}

// one layer: nchunks K-chunks of 64; A first part from (h1/x) then second.
// B fragments direct from packed gmem. acc[4][4] per warp (m16 x n32).
__device__ __forceinline__ void run_layer(
    uint32_t* sAh, uint32_t* sAl,
    int nchunks, int splitc,
    const __half* a1h, const __half* a1l, int str1,
    const __half* a2h, const __half* a2l,
    const uint4* pkA, int ktA, const uint4* pkB,   // kt split at ktA*? (ktsplit = splitc*4)
    int m0, int ub, float acc[4][4])
{
    int tid = threadIdx.x, lane = tid & 31, w = tid >> 5;
    int warpM = w & 3, nh = w >> 2;
    int ktsplit = splitc * 4;

#pragma unroll
    for (int nt = 0; nt < 4; nt++)
#pragma unroll
        for (int r = 0; r < 4; r++) acc[nt][r] = 0.f;

    uint4 ra[4];
    fetchA(a1h, a1l, str1, m0, ra);

#pragma unroll 1
    for (int c = 0; c < nchunks; c++) {
        __syncthreads();
        storeA(sAh, sAl, ra);
        __syncthreads();
        if (c + 1 < nchunks) {
            int cn = c + 1;
            if (cn < splitc) fetchA(a1h + cn * 64, a1l + cn * 64, str1, m0, ra);
            else             fetchA(a2h + (cn - splitc) * 64, a2l + (cn - splitc) * 64, NU, m0, ra);
        }
#pragma unroll
        for (int j = 0; j < 4; j++) {
            int ktL = c * 4 + j;
            const uint4* bp = (ktL < ktsplit)
                ? pkA + (((ub * ktA + ktL) * 8 + nh * 4) * 32 + lane)
                : pkB + (((ub * 32 + (ktL - ktsplit)) * 8 + nh * 4) * 32 + lane);
            uint4 bf0 = bp[0];
            uint4 bf1 = bp[32];
            uint4 bf2 = bp[64];
            uint4 bf3 = bp[96];

            int ab = (warpM * 16 + (lane >> 2)) * 36 + j * 8 + (lane & 3);
            uint32_t ah0 = sAh[ab],       ah1 = sAh[ab + 288];
            uint32_t ah2 = sAh[ab + 4],   ah3 = sAh[ab + 292];
            uint32_t al0 = sAl[ab],       al1 = sAl[ab + 288];
            uint32_t al2 = sAl[ab + 4],   al3 = sAl[ab + 292];

            MMA16816(acc[0], ah0, ah1, ah2, ah3, bf0.x, bf0.y);
            MMA16816(acc[1], ah0, ah1, ah2, ah3, bf1.x, bf1.y);
            MMA16816(acc[2], ah0, ah1, ah2, ah3, bf2.x, bf2.y);
            MMA16816(acc[3], ah0, ah1, ah2, ah3, bf3.x, bf3.y);
            MMA16816(acc[0], ah0, ah1, ah2, ah3, bf0.z, bf0.w);
            MMA16816(acc[1], ah0, ah1, ah2, ah3, bf1.z, bf1.w);
            MMA16816(acc[2], ah0, ah1, ah2, ah3, bf2.z, bf2.w);
            MMA16816(acc[3], ah0, ah1, ah2, ah3, bf3.z, bf3.w);
            MMA16816(acc[0], al0, al1, al2, al3, bf0.x, bf0.y);
            MMA16816(acc[1], al0, al1, al2, al3, bf1.x, bf1.y);
            MMA16816(acc[2], al0, al1, al2, al3, bf2.x, bf2.y);
            MMA16816(acc[3], al0, al1, al2, al3, bf3.x, bf3.y);
        }
    }
}

// epilogue: gate exchange via shfl_xor(1), cell update, write h hi/lo planes.
__device__ __forceinline__ void epilogue(float acc[4][4], float cst[4],
                                         const float* sb,
                                         __half* dsth, __half* dstl,
                                         int m0, int u0)
{
    int tid = threadIdx.x, lane = tid & 31, w = tid >> 5;
    int warpM = w & 3, nh = w >> 2;
    int gp = lane & 1;
    int rlow = m0 + warpM * 16 + (lane >> 2);
#pragma unroll
    for (int nt = 0; nt < 4; nt++) {
        float c0 = acc[nt][0], c1 = acc[nt][1], c2 = acc[nt][2], c3 = acc[nt][3];
        float e0 = __shfl_xor_sync(0xffffffffu, c0, 1);
        float e1 = __shfl_xor_sync(0xffffffffu, c1, 1);
        float e2 = __shfl_xor_sync(0xffffffffu, c2, 1);
        float e3 = __shfl_xor_sync(0xffffffffu, c3, 1);
        float zi, zf, zg, zo; int row;
        if (!gp) { zi = c0; zf = c1; zg = e0; zo = e1; row = rlow; }
        else     { zi = e2; zf = e3; zg = c2; zo = c3; row = rlow + 8; }
        int ul = nh * 8 + nt * 2 + ((lane >> 1) & 1);
        zi += sb[ul * 4 + 0]; zf += sb[ul * 4 + 1];
        zg += sb[ul * 4 + 2]; zo += sb[ul * 4 + 3];
        float cn = sigf(zf) * cst[nt] + sigf(zi) * tanhfast(zg);
        cst[nt] = cn;
        float h = sigf(zo) * tanhfast(cn);
        __half hh = __float2half(h);
        __half hl = __float2half(h - __half2float(hh));
        dsth[(size_t)row * NU + u0 + ul] = hh;
        dstl[(size_t)row * NU + u0 + ul] = hl;
    }
}

// ---------------------------------------------------------------------------
__global__ void __launch_bounds__(NTHR, 1) lstm_kernel(
    const float* __restrict__ b0, const float* __restrict__ b1)
{
    __shared__ __align__(16) uint32_t sAh[64 * 36];
    __shared__ __align__(16) uint32_t sAl[64 * 36];
    __shared__ float sb0[64], sb1[64];

    int tid = threadIdx.x;
    int bx = blockIdx.x;
    int ub = bx & 31, mb = bx >> 5;
    int u0 = ub * 16, m0 = mb * 64;

    if (tid < 64) {
        int f = tid >> 2, g = tid & 3;
        sb0[tid] = b0[g * NU + u0 + f];
        sb1[tid] = b1[g * NU + u0 + f];
    }
    __syncthreads();

    float cst0[4] = {0.f, 0.f, 0.f, 0.f};
    float cst1[4] = {0.f, 0.f, 0.f, 0.f};
    float acc[4][4];

    int slot = 0;
#pragma unroll 1
    for (int t = 0; t < TSEQ; t++) {
        int p = t & 1;
        const __half* h0ch = &g_h0h[p][0][0];     const __half* h0cl = &g_h0l[p][0][0];
        __half*       h0nh = &g_h0h[p ^ 1][0][0]; __half*       h0nl = &g_h0l[p ^ 1][0][0];
        const __half* h1ch = &g_h1h[p][0][0];     const __half* h1cl = &g_h1l[p][0][0];
        __half*       h1nh = &g_h1h[p ^ 1][0][0]; __half*       h1nl = &g_h1l[p ^ 1][0][0];

        // layer 0: A = [x_t (K=256) | h0c (K=512)], B = [W0pk ; U0pk]
        run_layer(sAh, sAl, 12, 4,
                  g_xh + t * DIN, g_xl + t * DIN, TSEQ * DIN,
                  h0ch, h0cl,
                  g_W0pk, 16, g_U0pk,
                  m0, ub, acc);
        epilogue(acc, cst0, sb0, h0nh, h0nl, m0, u0);
        gbar(slot++);

        // layer 1: A = [h0n (K=512) | h1c (K=512)], B = [W1pk ; U1pk]
        run_layer(sAh, sAl, 16, 8,
                  h0nh, h0nl, NU,
                  h1ch, h1cl,
                  g_W1pk, 32, g_U1pk,
                  m0, ub, acc);
        epilogue(acc, cst1, sb1, h1nh, h1nl, m0, u0);
        gbar(slot++);
    }
}

// Final head: out[b] = h1_final[b,:] @ Wfc + bfc. Final h1 is in plane buffer 0.
__global__ void out_kernel(const float* __restrict__ Wfc,
                           const float* __restrict__ bfc,
                           float* __restrict__ out)
{
    int warp = threadIdx.x >> 5, lane = threadIdx.x & 31;
    int wglob = blockIdx.x * 8 + warp;
#pragma unroll
    for (int i = 0; i < 4; i++) {
        int b = wglob * 4 + i;
        float s = 0.f;
        for (int u = lane; u < NU; u += 32) {
            float h = __half2float(g_h1h[0][b][u]) + __half2float(g_h1l[0][b][u]);
            s += h * Wfc[u];
        }
#pragma unroll
        for (int off = 16; off; off >>= 1) s += __shfl_down_sync(0xffffffffu, s, off);
        if (lane == 0) out[b] = s + bfc[0];
    }
}

extern "C" void kernel_launch(void* const* d_in, const int* in_sizes, int n_in,
                              void* d_out, int out_size)
{
    const float* x   = (const float*)d_in[0];
    const float* W0  = (const float*)d_in[1];
    const float* U0  = (const float*)d_in[2];
    const float* b0  = (const float*)d_in[3];
    const float* W1  = (const float*)d_in[4];
    const float* U1  = (const float*)d_in[5];
    const float* b1  = (const float*)d_in[6];
    const float* Wfc = (const float*)d_in[7];
    const float* bfc = (const float*)d_in[8];

    split_x_kernel<<<65536, 256>>>(x);
    pack_w_kernel<<<3584, 256>>>(W0, U0, W1, U1);
    lstm_kernel<<<NCTA, NTHR>>>(b0, b1);
    out_kernel<<<8, 256>>>(Wfc, bfc, (float*)d_out);
}